// round 3
// baseline (speedup 1.0000x reference)
#include <cuda_runtime.h>
#include <math.h>

#define N_POINTS   4194304
#define NUM_LEVELS 16
#define HASH_MASK  ((1u << 19) - 1u)
#define BLOCK      256
#define ROW_PAD    34   // 32 feats + 2 pad floats: keeps 8B alignment, 2-way STS conflict = crossbar floor

struct ResParams { float rm1[NUM_LEVELS]; };

#define L1_CUTOFF 6

__global__ __launch_bounds__(BLOCK)
void hashenc_kernel(const float*  __restrict__ pts,
                    const float*  __restrict__ tables,
                    float*        __restrict__ out,
                    ResParams rp)
{
    __shared__ float sm[BLOCK * ROW_PAD];

    const int t = threadIdx.x;
    const int n = blockIdx.x * BLOCK + t;

    const float x = __ldcs(pts + 3 * (size_t)n + 0);
    const float y = __ldcs(pts + 3 * (size_t)n + 1);
    const float z = __ldcs(pts + 3 * (size_t)n + 2);

    // normalize [-1,1] -> [0,1], clamp (matches jnp.clip((p+1)*0.5, 0, 1))
    const float fx = fminf(fmaxf((x + 1.0f) * 0.5f, 0.0f), 1.0f);
    const float fy = fminf(fmaxf((y + 1.0f) * 0.5f, 0.0f), 1.0f);
    const float fz = fminf(fmaxf((z + 1.0f) * 0.5f, 0.0f), 1.0f);

    // Phase 1: all 16 table pointers.
    const float2* p[NUM_LEVELS];
    #pragma unroll
    for (int l = 0; l < NUM_LEVELS; ++l) {
        const float rm1 = rp.rm1[l];
        const unsigned cx = (unsigned)(fx * rm1);   // trunc == floor (non-negative)
        const unsigned cy = (unsigned)(fy * rm1);
        const unsigned cz = (unsigned)(fz * rm1);
        const unsigned h = (cx ^ (cy * 2654435761u) ^ (cz * 805459861u)) & HASH_MASK;
        p[l] = reinterpret_cast<const float2*>(tables) + ((size_t)l << 19) + h;
    }

    // Phase 2: 16 independent gathers in flight, results staged to smem row.
    float2 feat[NUM_LEVELS];
    #pragma unroll
    for (int l = 0; l < NUM_LEVELS; ++l) {
        if (l < L1_CUTOFF) feat[l] = __ldg(p[l]);
        else               feat[l] = __ldcg(p[l]);
    }
    float2* row = reinterpret_cast<float2*>(sm + t * ROW_PAD);
    #pragma unroll
    for (int l = 0; l < NUM_LEVELS; ++l) row[l] = feat[l];

    // Phase 3: warp-local transpose copy-out. Each warp owns 32 consecutive
    // rows = 4KB contiguous GMEM; only intra-warp smem dependency -> syncwarp.
    __syncwarp();

    const int warp = t >> 5;
    const int lane = t & 31;
    // out base for this warp's 32 rows (in float2 units: 16 per row)
    float2* gout = reinterpret_cast<float2*>(out) +
                   ((size_t)(blockIdx.x * BLOCK + warp * 32)) * 16;
    const float* smw = sm + warp * 32 * ROW_PAD;

    #pragma unroll
    for (int i = 0; i < 16; ++i) {
        const int f2  = i * 32 + lane;        // float2 index within 32x16 chunk
        const int r   = f2 >> 4;              // source row within warp
        const int c2  = f2 & 15;              // float2 col
        const float2 v = *reinterpret_cast<const float2*>(smw + r * ROW_PAD + c2 * 2);
        __stcs(gout + f2, v);                 // coalesced 256B per instruction
    }
}

extern "C" void kernel_launch(void* const* d_in, const int* in_sizes, int n_in,
                              void* d_out, int out_size)
{
    (void)in_sizes; (void)n_in; (void)out_size;

    // numpy-identical resolution computation
    ResParams rp;
    const double l128 = log(128.0);
    for (int i = 0; i < NUM_LEVELS; ++i) {
        const int res = (int)floor(16.0 * exp(((double)i * l128) / 15.0));
        rp.rm1[i] = (float)(res - 1);
    }

    const float* pts    = (const float*)d_in[0];
    const float* tables = (const float*)d_in[1];
    float*       out    = (float*)d_out;

    hashenc_kernel<<<N_POINTS / BLOCK, BLOCK>>>(pts, tables, out, rp);
}